// round 16
// baseline (speedup 1.0000x reference)
#include <cuda_runtime.h>

#define HID   64
#define BATCH 16
#define SEQ   512
#define T_PER_BLK 16                      // tokens per gather block
#define NCHUNK (1024 / T_PER_BLK)         // 64 chunks per batch
#define NBLOCKS (BATCH * NCHUNK)          // 1024
#define W1T_STRIDE 65

// Per-batch hidden accumulator + completion counter. Static zero-init covers
// the first launch; the last block restores g_acc = 0 and g_done = 0 each
// launch, so the correctness run and every graph replay are self-consistent.
__device__ float g_acc[BATCH * HID];
__device__ int   g_done[1];

// ---------------------------------------------------------------- fused gather + MLP
// Gather phase (proven ~7.1 TB/s config): 256 threads, 16 tokens/block.
// Row = 1024 float4. Thread tid loads float4 f = tid + 256*j (j=0..3):
// w = (tid>>4)+16j, h = (tid&15)*4..+3 — one float4 accumulator/thread.
// Block partials -> 64 atomicAdds into g_acc. The LAST finishing block
// (threadfence-reduction) then runs the whole MLP in-place and cleans up.
__global__ __launch_bounds__(256) void fused_kernel(
    const int*   __restrict__ s1,
    const int*   __restrict__ s2,
    const float* __restrict__ embed,
    const float* __restrict__ sos,
    const float* __restrict__ w1,
    const float* __restrict__ b1,
    const float* __restrict__ w2,
    const float* __restrict__ b2,
    float*       __restrict__ out)
{
    __shared__ float  s_sos[HID];
    __shared__ int    s_tok[T_PER_BLK];
    __shared__ int    s_last;
    __shared__ union {
        float4 red[256];                          // gather reduction (4 KB)
        struct {                                  // last-block MLP (24.6 KB)
            float w1t[HID * W1T_STRIDE];
            float shh[BATCH * HID];
            float sxx[BATCH * HID];
        } m;
    } u;

    const int b   = blockIdx.x;           // batch
    const int c   = blockIdx.y;           // token chunk 0..63
    const int tid = threadIdx.x;

    if (tid < HID) s_sos[tid] = sos[tid];
    if (tid < T_PER_BLK) {
        const int l = c * T_PER_BLK + tid;        // 0..1023
        s_tok[tid] = (l < SEQ) ? s1[b * SEQ + l]
                               : s2[b * SEQ + (l - SEQ)];
    }
    __syncthreads();

    const int   wbase = tid >> 4;         // 0..15
    const float f0 = s_sos[wbase];
    const float fA = s_sos[wbase + 16];
    const float fB = s_sos[wbase + 32];
    const float fC = s_sos[wbase + 48];

    float4 acc = make_float4(0.f, 0.f, 0.f, 0.f);

    #pragma unroll 4
    for (int i = 0; i < T_PER_BLK; i++) {
        const float4* row = reinterpret_cast<const float4*>(embed)
                            + ((long long)s_tok[i] << 10);
        const float4 v0 = __ldg(&row[tid      ]);
        const float4 v1 = __ldg(&row[tid + 256]);
        const float4 v2 = __ldg(&row[tid + 512]);
        const float4 v3 = __ldg(&row[tid + 768]);
        acc.x = fmaf(f0, v0.x, acc.x); acc.y = fmaf(f0, v0.y, acc.y);
        acc.z = fmaf(f0, v0.z, acc.z); acc.w = fmaf(f0, v0.w, acc.w);
        acc.x = fmaf(fA, v1.x, acc.x); acc.y = fmaf(fA, v1.y, acc.y);
        acc.z = fmaf(fA, v1.z, acc.z); acc.w = fmaf(fA, v1.w, acc.w);
        acc.x = fmaf(fB, v2.x, acc.x); acc.y = fmaf(fB, v2.y, acc.y);
        acc.z = fmaf(fB, v2.z, acc.z); acc.w = fmaf(fB, v2.w, acc.w);
        acc.x = fmaf(fC, v3.x, acc.x); acc.y = fmaf(fC, v3.y, acc.y);
        acc.z = fmaf(fC, v3.z, acc.z); acc.w = fmaf(fC, v3.w, acc.w);
    }

    u.red[tid] = acc;
    __syncthreads();

    // 16 threads: h-group tid sums its 16 w-partials, 4 atomicAdds each.
    if (tid < 16) {
        float4 sum = make_float4(0.f, 0.f, 0.f, 0.f);
        #pragma unroll
        for (int j = 0; j < 16; j++) {
            const float4 v = u.red[tid + (j << 4)];
            sum.x += v.x; sum.y += v.y; sum.z += v.z; sum.w += v.w;
        }
        float* dst = &g_acc[b * HID + (tid << 2)];
        atomicAdd(dst + 0, sum.x);
        atomicAdd(dst + 1, sum.y);
        atomicAdd(dst + 2, sum.z);
        atomicAdd(dst + 3, sum.w);
    }
    __syncthreads();

    // Completion detection (threadfence-reduction pattern, proven in R14).
    if (tid == 0) {
        __threadfence();                          // publish this block's adds
        s_last = (atomicAdd(&g_done[0], 1) == NBLOCKS - 1) ? 1 : 0;
    }
    __syncthreads();
    if (!s_last) return;

    // ---------------- last block: full MLP for all 16 batches ----------------
    __threadfence();                              // acquire all blocks' adds

    // Stage w1 transposed (pad-65, conflict-free) + accumulated hiddens.
    #pragma unroll
    for (int j = 0; j < 16; j++) {
        const int idx = tid + 256 * j;            // 0..4095
        u.m.w1t[(idx & 63) * W1T_STRIDE + (idx >> 6)] = w1[idx];
    }
    #pragma unroll
    for (int j = 0; j < 4; j++) {
        const int id = tid + 256 * j;             // 0..1023
        u.m.shh[id] = g_acc[id];
        g_acc[id] = 0.0f;                         // restore for next replay
    }
    __syncthreads();

    // Layer 1 + ReLU: 1024 hidden units, 4 per thread.
    #pragma unroll
    for (int j = 0; j < 4; j++) {
        const int id = tid + 256 * j;
        const int bb = id >> 6;
        const int h  = id & 63;
        float sum = b1[h];
        const float* hb = &u.m.shh[bb * HID];
        #pragma unroll
        for (int k = 0; k < HID; k++)
            sum = fmaf(hb[k], u.m.w1t[k * W1T_STRIDE + h], sum);
        u.m.sxx[id] = fmaxf(sum, 0.0f);
    }
    __syncthreads();

    // Layer 2: 32 outputs.
    if (tid < BATCH * 2) {
        const int bb = tid >> 1;
        const int o  = tid & 1;
        float s = b2[o];
        #pragma unroll
        for (int k = 0; k < HID; k++)
            s = fmaf(u.m.sxx[bb * HID + k], w2[o * HID + k], s);
        out[bb * 2 + o] = s;
    }

    if (tid == 0) g_done[0] = 0;                  // reset for next replay
}

extern "C" void kernel_launch(void* const* d_in, const int* in_sizes, int n_in,
                              void* d_out, int out_size)
{
    const int*   s1    = (const int*)  d_in[0];
    const int*   s2    = (const int*)  d_in[1];
    const float* embed = (const float*)d_in[2];
    const float* sos   = (const float*)d_in[3];
    const float* w1    = (const float*)d_in[4];
    const float* b1    = (const float*)d_in[5];
    const float* w2    = (const float*)d_in[6];
    const float* b2    = (const float*)d_in[7];
    float* out = (float*)d_out;

    dim3 grid(BATCH, NCHUNK);
    fused_kernel<<<grid, 256>>>(s1, s2, embed, sos, w1, b1, w2, b2, out);
}